// round 6
// baseline (speedup 1.0000x reference)
#include <cuda_runtime.h>
#include <cuda_bf16.h>
#include <math.h>
#include <stdint.h>

#define NNODE 100000
#define NEDGE 200000
#define NGRAPH 4096
#define D 300
#define NLAYER 5
#define HDIM 600
#define DECH 1200
#define MAXO 1783
#define D4 (D/4)

// ---------------- scratch arenas (no cudaMalloc allowed) ----------------
#define OFF_H     0ull
#define OFF_Z     30000000ull
#define OFF_Z1    60000000ull
#define OFF_Z2    120000000ull
#define OFF_HG    150000000ull
#define OFF_MU    151228800ull
#define OFF_ZDEC  152457600ull
#define OFF_STATS 157372800ull
#define OFF_BNA   157375232ull
#define OFF_BNB   157376448ull
#define SCRATCH_FLOATS 157377664ull

__device__ float g_scratch[SCRATCH_FLOATS];

// bf16 split operands
// A': [M][3*Kpad] bf16, max 100000 x 1824
__device__ __align__(16) unsigned short g_abf[182400000];
// W': w1 per layer 640*912, then w2 per layer 384*1824
#define WBF_W1(l) ((size_t)(l) * 583680)
#define WBF_W2(l) (2918400ull + (size_t)(l) * 700416)
__device__ __align__(16) unsigned short g_wbf[6420480];

typedef unsigned long long u64;

#define FMA2(acc, a2, b2) \
    asm("fma.rn.f32x2 %0, %1, %2, %0;" : "+l"(acc) : "l"(a2), "l"(b2))
#define DUP2(d, x) \
    asm("mov.b64 %0, {%1, %1};" : "=l"(d) : "f"(x))
#define UNPACK2(lo, hi, v) \
    asm("mov.b64 {%0, %1}, %2;" : "=f"(lo), "=f"(hi) : "l"(v))

__device__ __forceinline__ uint32_t smem_u32(const void* p) {
    uint32_t a;
    asm("{ .reg .u64 t; cvta.to.shared.u64 t, %1; cvt.u32.u64 %0, t; }" : "=r"(a) : "l"(p));
    return a;
}

#define LDSM4(r, addr) \
    asm volatile("ldmatrix.sync.aligned.m8n8.x4.shared.b16 {%0,%1,%2,%3}, [%4];" \
        : "=r"((r)[0]), "=r"((r)[1]), "=r"((r)[2]), "=r"((r)[3]) : "r"(addr))

#define MMA_BF16(d, a, b0, b1) \
    asm volatile("mma.sync.aligned.m16n8k16.row.col.f32.bf16.bf16.f32 " \
        "{%0,%1,%2,%3}, {%4,%5,%6,%7}, {%8,%9}, {%0,%1,%2,%3};" \
        : "+f"((d)[0]), "+f"((d)[1]), "+f"((d)[2]), "+f"((d)[3]) \
        : "r"((a)[0]), "r"((a)[1]), "r"((a)[2]), "r"((a)[3]), "r"(b0), "r"(b1))

#define CPASYNC16(dst, src, sz) \
    asm volatile("cp.async.cg.shared.global [%0], [%1], 16, %2;" \
        :: "r"(dst), "l"(src), "r"(sz))
#define CPCOMMIT() asm volatile("cp.async.commit_group;")
#define CPWAIT1()  asm volatile("cp.async.wait_group 1;")
#define CPWAIT0()  asm volatile("cp.async.wait_group 0;")

// ---------------- small elementwise kernels ----------------

__global__ void k_gather(const float* __restrict__ atom_emb,
                         const int* __restrict__ x_idx,
                         float* __restrict__ h) {
    int t = blockIdx.x * blockDim.x + threadIdx.x;
    if (t >= NNODE * D4) return;
    int i = t / D4;
    int c = (t - i * D4) * 4;
    int a = x_idx[i];
    float4 v = *reinterpret_cast<const float4*>(atom_emb + (size_t)a * D + c);
    *reinterpret_cast<float4*>(h + (size_t)i * D + c) = v;
}

__global__ void k_scale(const float* __restrict__ h,
                        const float* __restrict__ eps, int l,
                        float* __restrict__ z) {
    int t = blockIdx.x * blockDim.x + threadIdx.x;
    if (t >= NNODE * D4) return;
    float s = 1.0f + eps[l];
    float4 v = *reinterpret_cast<const float4*>(h + (size_t)t * 4);
    v.x *= s; v.y *= s; v.z *= s; v.w *= s;
    *reinterpret_cast<float4*>(z + (size_t)t * 4) = v;
}

__global__ void k_edge(const float* __restrict__ h,
                       const float* __restrict__ emb,
                       const int* __restrict__ attr,
                       const int* __restrict__ eidx,
                       float* __restrict__ z) {
    int t = blockIdx.x * blockDim.x + threadIdx.x;
    if (t >= NEDGE * D4) return;
    int e = t / D4;
    int c = (t - e * D4) * 4;
    int src = eidx[e];
    int dst = eidx[NEDGE + e];
    int a = attr[e];
    float4 hv = *reinterpret_cast<const float4*>(h + (size_t)src * D + c);
    float4 ev = *reinterpret_cast<const float4*>(emb + (size_t)a * D + c);
    float m0 = fmaxf(hv.x + ev.x, 0.0f);
    float m1 = fmaxf(hv.y + ev.y, 0.0f);
    float m2 = fmaxf(hv.z + ev.z, 0.0f);
    float m3 = fmaxf(hv.w + ev.w, 0.0f);
    float* zp = z + (size_t)dst * D + c;
    atomicAdd(zp + 0, m0);
    atomicAdd(zp + 1, m1);
    atomicAdd(zp + 2, m2);
    atomicAdd(zp + 3, m3);
}

__global__ void k_zero(float* __restrict__ p, int n) {
    int t = blockIdx.x * blockDim.x + threadIdx.x;
    if (t < n) p[t] = 0.0f;
}

#define RED_ROWS 512
__global__ void k_colreduce(const float* __restrict__ X, int M, int Nc,
                            float* __restrict__ stats) {
    int c = blockIdx.x * blockDim.x + threadIdx.x;
    if (c >= Nc) return;
    int r0 = blockIdx.y * RED_ROWS;
    int r1 = r0 + RED_ROWS; if (r1 > M) r1 = M;
    float s = 0.0f, s2 = 0.0f;
    for (int r = r0; r < r1; r++) {
        float v = X[(size_t)r * Nc + c];
        s += v;
        s2 += v * v;
    }
    atomicAdd(&stats[c], s);
    atomicAdd(&stats[Nc + c], s2);
}

__global__ void k_bnparam(const float* __restrict__ stats,
                          const float* __restrict__ g,
                          const float* __restrict__ b,
                          int Nc, float invM,
                          float* __restrict__ bnA, float* __restrict__ bnB) {
    int c = blockIdx.x * blockDim.x + threadIdx.x;
    if (c >= Nc) return;
    float mean = stats[c] * invM;
    float var = stats[Nc + c] * invM - mean * mean;
    float a = g[c] * rsqrtf(var + 1e-5f);
    bnA[c] = a;
    bnB[c] = b[c] - mean * a;
}

__global__ void k_finalize(const float* __restrict__ z2,
                           const float* __restrict__ bnA,
                           const float* __restrict__ bnB,
                           int dorelu, float* __restrict__ h) {
    int t = blockIdx.x * blockDim.x + threadIdx.x;
    if (t >= NNODE * D4) return;
    size_t base = (size_t)t * 4;
    int c = (int)(base % D);
    float4 zv = *reinterpret_cast<const float4*>(z2 + base);
    float4 hv = *reinterpret_cast<const float4*>(h + base);
    float v0 = bnA[c + 0] * zv.x + bnB[c + 0];
    float v1 = bnA[c + 1] * zv.y + bnB[c + 1];
    float v2 = bnA[c + 2] * zv.z + bnB[c + 2];
    float v3 = bnA[c + 3] * zv.w + bnB[c + 3];
    if (dorelu) {
        v0 = fmaxf(v0, 0.0f); v1 = fmaxf(v1, 0.0f);
        v2 = fmaxf(v2, 0.0f); v3 = fmaxf(v3, 0.0f);
    }
    hv.x += v0; hv.y += v1; hv.z += v2; hv.w += v3;
    *reinterpret_cast<float4*>(h + base) = hv;
}

__global__ void k_hginit(float* __restrict__ hg) {
    int t = blockIdx.x * blockDim.x + threadIdx.x;
    if (t < NGRAPH * D) hg[t] = -INFINITY;
}

__device__ __forceinline__ void atomicMaxF(float* addr, float v) {
    if (v >= 0.0f) atomicMax((int*)addr, __float_as_int(v));
    else atomicMin((unsigned int*)addr, __float_as_uint(v));
}

__global__ void k_segmax(const float* __restrict__ h,
                         const int* __restrict__ batch,
                         float* __restrict__ hg) {
    int t = blockIdx.x * blockDim.x + threadIdx.x;
    if (t >= NNODE * D4) return;
    int i = t / D4;
    int c = (t - i * D4) * 4;
    int g = batch[i];
    float4 v = *reinterpret_cast<const float4*>(h + (size_t)i * D + c);
    float* p = hg + (size_t)g * D + c;
    atomicMaxF(p + 0, v.x);
    atomicMaxF(p + 1, v.y);
    atomicMaxF(p + 2, v.z);
    atomicMaxF(p + 3, v.w);
}

// ---------------- bf16 split conversion ----------------

__device__ __forceinline__ unsigned pk2bf(float a, float b) {
    unsigned short ua = __bfloat16_as_ushort(__float2bfloat16(a));
    unsigned short ub = __bfloat16_as_ushort(__float2bfloat16(b));
    return (unsigned)ua | ((unsigned)ub << 16);
}

// A': sections [Ah | Al | Ah]. PRE: 0 none, 1 bn+relu
template <int PRE>
__global__ void k_convA_bf(const float* __restrict__ X, int ldx, int Kin, int Kpad,
                           int Mrows,
                           const float* __restrict__ bnA, const float* __restrict__ bnB,
                           unsigned short* __restrict__ out, int kpitch) {
    int groups = Kpad >> 3;
    int t = blockIdx.x * blockDim.x + threadIdx.x;
    if (t >= Mrows * groups) return;
    int m = t / groups;
    int ko = (t - m * groups) << 3;
    const float* xr = X + (size_t)m * ldx;
    float hi[8], lo[8];
#pragma unroll
    for (int j = 0; j < 8; j++) {
        int k = ko + j;
        float x = 0.0f;
        if (k < Kin) {
            x = xr[k];
            if (PRE == 1) x = fmaxf(fmaf(bnA[k], x, bnB[k]), 0.0f);
        }
        __nv_bfloat16 h = __float2bfloat16(x);
        float hf = __bfloat162float(h);
        hi[j] = hf;
        lo[j] = x - hf;
    }
    uint4 H, L;
    H.x = pk2bf(hi[0], hi[1]); H.y = pk2bf(hi[2], hi[3]);
    H.z = pk2bf(hi[4], hi[5]); H.w = pk2bf(hi[6], hi[7]);
    L.x = pk2bf(lo[0], lo[1]); L.y = pk2bf(lo[2], lo[3]);
    L.z = pk2bf(lo[4], lo[5]); L.w = pk2bf(lo[6], lo[7]);
    unsigned short* row = out + (size_t)m * kpitch + ko;
    *reinterpret_cast<uint4*>(row) = H;
    *reinterpret_cast<uint4*>(row + Kpad) = L;
    *reinterpret_cast<uint4*>(row + 2 * Kpad) = H;
}

// W': stored [Npad][3*Kpad] (n-major), sections [Bh | Bh | Bl]
__global__ void k_convW_bf(const float* __restrict__ W, int ldw, int Kin, int Kpad,
                           int Nout, int Npad, unsigned short* __restrict__ out) {
    int groups = Kpad >> 3;
    int t = blockIdx.x * blockDim.x + threadIdx.x;
    if (t >= Npad * groups) return;
    int n = t / groups;
    int ko = (t - n * groups) << 3;
    float hi[8], lo[8];
#pragma unroll
    for (int j = 0; j < 8; j++) {
        int k = ko + j;
        float x = (n < Nout && k < Kin) ? W[(size_t)k * ldw + n] : 0.0f;
        __nv_bfloat16 h = __float2bfloat16(x);
        float hf = __bfloat162float(h);
        hi[j] = hf;
        lo[j] = x - hf;
    }
    uint4 H, L;
    H.x = pk2bf(hi[0], hi[1]); H.y = pk2bf(hi[2], hi[3]);
    H.z = pk2bf(hi[4], hi[5]); H.w = pk2bf(hi[6], hi[7]);
    L.x = pk2bf(lo[0], lo[1]); L.y = pk2bf(lo[2], lo[3]);
    L.z = pk2bf(lo[4], lo[5]); L.w = pk2bf(lo[6], lo[7]);
    int kpitch = 3 * Kpad;
    unsigned short* row = out + (size_t)n * kpitch + ko;
    *reinterpret_cast<uint4*>(row) = H;
    *reinterpret_cast<uint4*>(row + Kpad) = H;
    *reinterpret_cast<uint4*>(row + 2 * Kpad) = L;
}

// ---------------- HMMA GEMM: CTA 128x128, 8 warps x (64x32), k16 slabs --------
// C[r*ldc + c] = sum_k A'[r][k]*B'[c][k] + bias[c]
// smem rows padded to 48B (16 bf16 data + 16B pad) -> conflict-free ldmatrix.

__global__ void __launch_bounds__(256, 2)
k_hmma(const unsigned short* __restrict__ Ab, const unsigned short* __restrict__ Bb,
       const float* __restrict__ bias, float* __restrict__ C,
       int M, int Nreal, int ldc, int kpitch, int nk) {
    __shared__ __align__(16) char smem[24576];
    uint32_t sb = smem_u32(smem);
    int tid = threadIdx.x;
    int lane = tid & 31;
    int warp = tid >> 5;
    int wm = warp & 1;
    int wn = warp >> 1;
    int mtile = blockIdx.y;
    int ntile = blockIdx.x;

    int lrow = tid >> 1;
    int lhalf = tid & 1;

    const char* Ag = (const char*)(Ab + (size_t)(mtile * 128 + lrow) * kpitch) + lhalf * 16;
    const char* Bg = (const char*)(Bb + (size_t)(ntile * 128 + lrow) * kpitch) + lhalf * 16;
    unsigned asz = ((mtile * 128 + lrow) < M) ? 16u : 0u;
    uint32_t sA = sb + lrow * 48 + lhalf * 16;
    uint32_t sB = sb + 6144 + lrow * 48 + lhalf * 16;

    float acc[4][4][4];
#pragma unroll
    for (int i = 0; i < 4; i++)
#pragma unroll
        for (int j = 0; j < 4; j++)
#pragma unroll
            for (int q = 0; q < 4; q++) acc[i][j][q] = 0.0f;

    // prologue: slab 0 -> buf 0
    CPASYNC16(sA, Ag, asz);
    CPASYNC16(sB, Bg, 16u);
    CPCOMMIT();

    uint32_t aoff = sb + (wm * 64 + (lane & 15)) * 48 + (lane >> 4) * 16;
    uint32_t boff = sb + 6144 + (wn * 32 + (lane & 15)) * 48 + (lane >> 4) * 16;

    for (int kt = 0; kt < nk; kt++) {
        int buf = kt & 1;
        if (kt + 1 < nk) {
            int nb = (kt + 1) & 1;
            const char* a2 = Ag + (size_t)(kt + 1) * 32;
            const char* b2 = Bg + (size_t)(kt + 1) * 32;
            CPASYNC16(sA + nb * 12288, a2, asz);
            CPASYNC16(sB + nb * 12288, b2, 16u);
            CPCOMMIT();
            CPWAIT1();
        } else {
            CPWAIT0();
        }
        __syncthreads();

        uint32_t a[4][4], b[2][4];
        uint32_t abase = aoff + buf * 12288;
        uint32_t bbase = boff + buf * 12288;
#pragma unroll
        for (int mi = 0; mi < 4; mi++)
            LDSM4(a[mi], abase + mi * 768);
#pragma unroll
        for (int j = 0; j < 2; j++)
            LDSM4(b[j], bbase + j * 768);

#pragma unroll
        for (int mi = 0; mi < 4; mi++)
#pragma unroll
            for (int nj = 0; nj < 4; nj++) {
                uint32_t b0 = (nj & 1) ? b[nj >> 1][1] : b[nj >> 1][0];
                uint32_t b1 = (nj & 1) ? b[nj >> 1][3] : b[nj >> 1][2];
                MMA_BF16(acc[mi][nj], a[mi], b0, b1);
            }
        __syncthreads();
    }

    // epilogue
    int g = lane >> 2, tig = lane & 3;
#pragma unroll
    for (int nj = 0; nj < 4; nj++) {
        int c = ntile * 128 + wn * 32 + nj * 8 + tig * 2;
        if (c >= Nreal) continue;            // c even, Nreal even -> c+1 < Nreal
        float bc0 = bias[c], bc1 = bias[c + 1];
#pragma unroll
        for (int mi = 0; mi < 4; mi++) {
            int r0 = mtile * 128 + wm * 64 + mi * 16 + g;
            if (r0 < M) {
                float2 v;
                v.x = acc[mi][nj][0] + bc0;
                v.y = acc[mi][nj][1] + bc1;
                *reinterpret_cast<float2*>(C + (size_t)r0 * ldc + c) = v;
            }
            int r1 = r0 + 8;
            if (r1 < M) {
                float2 v;
                v.x = acc[mi][nj][2] + bc0;
                v.y = acc[mi][nj][3] + bc1;
                *reinterpret_cast<float2*>(C + (size_t)r1 * ldc + c) = v;
            }
        }
    }
}

// ---------------- SIMT GEMM (kept for dist + decoder heads) ----------------

#define MODE_PLAIN 0
#define MODE_BNRELU 1
#define MODE_DIST 2
#define MODE_DEC 3

#define BM 128
#define BN 128
#define BK 8

template <int MODE>
__device__ __forceinline__ void preprocA(float4& av, int gk,
                                         const float* __restrict__ bnA,
                                         const float* __restrict__ bnB) {
    if (MODE == MODE_BNRELU) {
        av.x = fmaxf(fmaf(bnA[gk + 0], av.x, bnB[gk + 0]), 0.0f);
        av.y = fmaxf(fmaf(bnA[gk + 1], av.y, bnB[gk + 1]), 0.0f);
        av.z = fmaxf(fmaf(bnA[gk + 2], av.z, bnB[gk + 2]), 0.0f);
        av.w = fmaxf(fmaf(bnA[gk + 3], av.w, bnB[gk + 3]), 0.0f);
    } else if (MODE == MODE_DIST) {
        av.x = av.x / (1.0f + expf(-av.x));
        av.y = av.y / (1.0f + expf(-av.y));
        av.z = av.z / (1.0f + expf(-av.z));
        av.w = av.w / (1.0f + expf(-av.w));
    } else if (MODE == MODE_DEC) {
        float t0 = fmaf(bnA[gk + 0], av.x, bnB[gk + 0]);
        float t1 = fmaf(bnA[gk + 1], av.y, bnB[gk + 1]);
        float t2 = fmaf(bnA[gk + 2], av.z, bnB[gk + 2]);
        float t3 = fmaf(bnA[gk + 3], av.w, bnB[gk + 3]);
        av.x = 0.5f * t0 * (1.0f + erff(t0 * 0.70710678118654752f));
        av.y = 0.5f * t1 * (1.0f + erff(t1 * 0.70710678118654752f));
        av.z = 0.5f * t2 * (1.0f + erff(t2 * 0.70710678118654752f));
        av.w = 0.5f * t3 * (1.0f + erff(t3 * 0.70710678118654752f));
    }
}

template <int MODE, bool VECB>
__global__ void __launch_bounds__(256, 2)
k_gemm(const float* __restrict__ A, const float* __restrict__ B,
       const float* __restrict__ bias,
       float* __restrict__ C, float* __restrict__ C2, float* __restrict__ C3,
       int M, int N, int K, int ldb, int NB, int ldc,
       const float* __restrict__ bnA, const float* __restrict__ bnB) {
    __shared__ __align__(16) float As[2][BK][BM];
    __shared__ __align__(16) float Bs[2][BK][BN];
    int tid = threadIdx.x;
    int row0 = blockIdx.y * BM;
    int col0 = blockIdx.x * BN;
    int tx = tid & 15, ty = tid >> 4;

    int arow = tid >> 1;
    int ak = (tid & 1) << 2;
    int bkr = tid >> 5;
    int bc = (tid & 31) << 2;

    int gr = row0 + arow;
    bool rowok = (gr < M);
    const float* Arow = A + (size_t)gr * K;

    u64 acc2[8][4];
#pragma unroll
    for (int i = 0; i < 8; i++)
#pragma unroll
        for (int j = 0; j < 4; j++) acc2[i][j] = 0ull;

    const int ktiles = (K + BK - 1) / BK;

    float4 av;
    float bv0, bv1, bv2, bv3;
    {
        int gk = ak;
        av = make_float4(0.f, 0.f, 0.f, 0.f);
        if (rowok && gk < K) {
            av = *reinterpret_cast<const float4*>(Arow + gk);
            preprocA<MODE>(av, gk, bnA, bnB);
        }
        int gkb = bkr;
        if (VECB) {
            float4 b4 = make_float4(0.f, 0.f, 0.f, 0.f);
            if (gkb < K && (col0 + bc) < NB)
                b4 = *reinterpret_cast<const float4*>(B + (size_t)gkb * ldb + col0 + bc);
            bv0 = b4.x; bv1 = b4.y; bv2 = b4.z; bv3 = b4.w;
        } else {
            const float* Bp = B + (size_t)gkb * ldb + col0 + bc;
            bool kok = (gkb < K);
            bv0 = (kok && col0 + bc + 0 < NB) ? Bp[0] : 0.0f;
            bv1 = (kok && col0 + bc + 1 < NB) ? Bp[1] : 0.0f;
            bv2 = (kok && col0 + bc + 2 < NB) ? Bp[2] : 0.0f;
            bv3 = (kok && col0 + bc + 3 < NB) ? Bp[3] : 0.0f;
        }
    }
    As[0][ak + 0][arow] = av.x;
    As[0][ak + 1][arow] = av.y;
    As[0][ak + 2][arow] = av.z;
    As[0][ak + 3][arow] = av.w;
    Bs[0][bkr][bc + 0] = bv0;
    Bs[0][bkr][bc + 1] = bv1;
    Bs[0][bkr][bc + 2] = bv2;
    Bs[0][bkr][bc + 3] = bv3;
    __syncthreads();

    int buf = 0;
    for (int t = 0; t < ktiles; t++) {
        bool has = (t + 1 < ktiles);
        if (has) {
            int gk = (t + 1) * BK + ak;
            av = make_float4(0.f, 0.f, 0.f, 0.f);
            if (rowok && gk < K) {
                av = *reinterpret_cast<const float4*>(Arow + gk);
                preprocA<MODE>(av, gk, bnA, bnB);
            }
            int gkb = (t + 1) * BK + bkr;
            if (VECB) {
                float4 b4 = make_float4(0.f, 0.f, 0.f, 0.f);
                if (gkb < K && (col0 + bc) < NB)
                    b4 = *reinterpret_cast<const float4*>(B + (size_t)gkb * ldb + col0 + bc);
                bv0 = b4.x; bv1 = b4.y; bv2 = b4.z; bv3 = b4.w;
            } else {
                const float* Bp = B + (size_t)gkb * ldb + col0 + bc;
                bool kok = (gkb < K);
                bv0 = (kok && col0 + bc + 0 < NB) ? Bp[0] : 0.0f;
                bv1 = (kok && col0 + bc + 1 < NB) ? Bp[1] : 0.0f;
                bv2 = (kok && col0 + bc + 2 < NB) ? Bp[2] : 0.0f;
                bv3 = (kok && col0 + bc + 3 < NB) ? Bp[3] : 0.0f;
            }
        }

#pragma unroll
        for (int kk = 0; kk < BK; kk++) {
            float4 a0 = *reinterpret_cast<const float4*>(&As[buf][kk][ty * 8]);
            float4 a1 = *reinterpret_cast<const float4*>(&As[buf][kk][ty * 8 + 4]);
            ulonglong2 bq0 = *reinterpret_cast<const ulonglong2*>(&Bs[buf][kk][tx * 8]);
            ulonglong2 bq1 = *reinterpret_cast<const ulonglong2*>(&Bs[buf][kk][tx * 8 + 4]);
            u64 b2[4] = {bq0.x, bq0.y, bq1.x, bq1.y};
            float a[8] = {a0.x, a0.y, a0.z, a0.w, a1.x, a1.y, a1.z, a1.w};
#pragma unroll
            for (int i = 0; i < 8; i++) {
                u64 a2;
                DUP2(a2, a[i]);
#pragma unroll
                for (int j = 0; j < 4; j++)
                    FMA2(acc2[i][j], a2, b2[j]);
            }
        }

        if (has) {
            int nb = buf ^ 1;
            As[nb][ak + 0][arow] = av.x;
            As[nb][ak + 1][arow] = av.y;
            As[nb][ak + 2][arow] = av.z;
            As[nb][ak + 3][arow] = av.w;
            Bs[nb][bkr][bc + 0] = bv0;
            Bs[nb][bkr][bc + 1] = bv1;
            Bs[nb][bkr][bc + 2] = bv2;
            Bs[nb][bkr][bc + 3] = bv3;
            __syncthreads();
            buf = nb;
        }
    }

#pragma unroll
    for (int i = 0; i < 8; i++) {
        int r = row0 + ty * 8 + i;
        if (r >= M) continue;
        float accf[8];
#pragma unroll
        for (int j = 0; j < 4; j++)
            UNPACK2(accf[2 * j], accf[2 * j + 1], acc2[i][j]);
#pragma unroll
        for (int j = 0; j < 8; j++) {
            int c = col0 + tx * 8 + j;
            if (c >= N) continue;
            float v = accf[j] + bias[c];
            if (MODE == MODE_DIST) {
                if (c < D) {
                    C[(size_t)r * ldc + c] = v;
                    C3[(size_t)r * D + c] = v;
                } else {
                    float sp = fmaxf(v, 0.0f) + log1pf(expf(-fabsf(v))) + 1e-7f;
                    C2[(size_t)r * ldc + (c - D)] = sp;
                }
            } else {
                C[(size_t)r * ldc + c] = v;
            }
        }
    }
}

// ---------------- host side ----------------

extern "C" void kernel_launch(void* const* d_in, const int* in_sizes, int n_in,
                              void* d_out, int out_size) {
    const float* atom_emb = (const float*)d_in[0];
    const float* edge_emb = (const float*)d_in[1];
    const float* eps      = (const float*)d_in[2];
    const float* conv_w1  = (const float*)d_in[3];
    const float* conv_b1  = (const float*)d_in[4];
    const float* bn1g     = (const float*)d_in[5];
    const float* bn1b     = (const float*)d_in[6];
    const float* conv_w2  = (const float*)d_in[7];
    const float* conv_b2  = (const float*)d_in[8];
    const float* bn_g     = (const float*)d_in[9];
    const float* bn_b     = (const float*)d_in[10];
    const float* dist_w   = (const float*)d_in[11];
    const float* dist_b   = (const float*)d_in[12];
    const float* dec_w1   = (const float*)d_in[13];
    const float* dec_b1   = (const float*)d_in[14];
    const float* dec_bng  = (const float*)d_in[15];
    const float* dec_bnb  = (const float*)d_in[16];
    const float* dec_w2   = (const float*)d_in[17];
    const float* dec_b2   = (const float*)d_in[18];
    const int* x_idx      = (const int*)d_in[19];
    const int* edge_attr  = (const int*)d_in[20];
    const int* edge_index = (const int*)d_in[21];
    const int* batch      = (const int*)d_in[22];
    float* out = (float*)d_out;

    void* sp = nullptr;
    cudaGetSymbolAddress(&sp, g_scratch);
    float* S = (float*)sp;
    float* h     = S + OFF_H;
    float* z     = S + OFF_Z;
    float* z1    = S + OFF_Z1;
    float* z2    = S + OFF_Z2;
    float* hg    = S + OFF_HG;
    float* mu    = S + OFF_MU;
    float* zdec  = S + OFF_ZDEC;
    float* stats = S + OFF_STATS;
    float* bnA   = S + OFF_BNA;
    float* bnB   = S + OFF_BNB;

    void* abp = nullptr; cudaGetSymbolAddress(&abp, g_abf);
    unsigned short* abf = (unsigned short*)abp;
    void* wbp = nullptr; cudaGetSymbolAddress(&wbp, g_wbf);
    unsigned short* wbf = (unsigned short*)wbp;

    const int TB = 256;
    const int gNode = (NNODE * D4 + TB - 1) / TB;
    const int gEdge = (NEDGE * D4 + TB - 1) / TB;
    const int MT_N = (NNODE + 127) / 128;   // 782

    // ---- convert encoder weights to split-bf16 (deterministic, every call) ----
    for (int l = 0; l < NLAYER; l++) {
        // w1: [300 x 600] -> [640][3*304]
        int n1 = 640 * (304 / 8);
        k_convW_bf<<<(n1 + TB - 1) / TB, TB>>>(conv_w1 + (size_t)l * D * HDIM, HDIM,
                                               300, 304, 600, 640, wbf + WBF_W1(l));
        // w2: [600 x 300] -> [384][3*608]
        int n2 = 384 * (608 / 8);
        k_convW_bf<<<(n2 + TB - 1) / TB, TB>>>(conv_w2 + (size_t)l * HDIM * D, D,
                                               600, 608, 300, 384, wbf + WBF_W2(l));
    }

    // ---- encoder ----
    k_gather<<<gNode, TB>>>(atom_emb, x_idx, h);

    for (int l = 0; l < NLAYER; l++) {
        k_scale<<<gNode, TB>>>(h, eps, l, z);
        k_edge<<<gEdge, TB>>>(h, edge_emb + (size_t)l * 5 * D, edge_attr, edge_index, z);

        // z1 = z @ w1 + b1  (HMMA split-bf16)
        {
            int nt = NNODE * (304 / 8);
            k_convA_bf<0><<<(nt + TB - 1) / TB, TB>>>(z, D, 300, 304, NNODE,
                                                      nullptr, nullptr, abf, 912);
            k_hmma<<<dim3(5, MT_N), 256>>>(abf, wbf + WBF_W1(l),
                                           conv_b1 + (size_t)l * HDIM, z1,
                                           NNODE, 600, 600, 912, 57);
        }
        k_zero<<<(2432 + TB - 1) / TB, TB>>>(stats, 2432);
        dim3 gr1((HDIM + TB - 1) / TB, (NNODE + RED_ROWS - 1) / RED_ROWS);
        k_colreduce<<<gr1, TB>>>(z1, NNODE, HDIM, stats);
        k_bnparam<<<(HDIM + TB - 1) / TB, TB>>>(stats, bn1g + (size_t)l * HDIM,
                                                bn1b + (size_t)l * HDIM,
                                                HDIM, 1.0f / NNODE, bnA, bnB);
        // z2 = relu(bn(z1)) @ w2 + b2  (HMMA split-bf16, BN+ReLU fused into conv)
        {
            int nt = NNODE * (608 / 8);
            k_convA_bf<1><<<(nt + TB - 1) / TB, TB>>>(z1, HDIM, 600, 608, NNODE,
                                                      bnA, bnB, abf, 1824);
            k_hmma<<<dim3(3, MT_N), 256>>>(abf, wbf + WBF_W2(l),
                                           conv_b2 + (size_t)l * D, z2,
                                           NNODE, 300, 300, 1824, 114);
        }
        k_zero<<<(2432 + TB - 1) / TB, TB>>>(stats, 2432);
        dim3 gr2((D + TB - 1) / TB, (NNODE + RED_ROWS - 1) / RED_ROWS);
        k_colreduce<<<gr2, TB>>>(z2, NNODE, D, stats);
        k_bnparam<<<(D + TB - 1) / TB, TB>>>(stats, bn_g + (size_t)l * D,
                                             bn_b + (size_t)l * D,
                                             D, 1.0f / NNODE, bnA, bnB);
        k_finalize<<<gNode, TB>>>(z2, bnA, bnB, (l < NLAYER - 1) ? 1 : 0, h);
    }

    k_hginit<<<(NGRAPH * D + TB - 1) / TB, TB>>>(hg);
    k_segmax<<<gNode, TB>>>(h, batch, hg);

    {
        dim3 gd((HDIM + BN - 1) / BN, (NGRAPH + BM - 1) / BM);
        k_gemm<MODE_DIST, true><<<gd, 256>>>(hg, dist_w, dist_b,
                                       out,
                                       out + (size_t)NGRAPH * D,
                                       mu,
                                       NGRAPH, HDIM, D, HDIM, HDIM, D,
                                       nullptr, nullptr);
    }

    const int ddims[6] = {1024, 1111, 862, 1783, 966, 978};
    const size_t dbase[6] = {
        2457600ull,
        6651904ull,
        6651904ull + 1111ull,
        14733312ull,
        14733312ull + 1783ull,
        25993216ull
    };
    const int dldc[6] = {1024, 1973, 1973, 2749, 2749, 978};

    for (int i = 0; i < 6; i++) {
        dim3 gd1((DECH + BN - 1) / BN, (NGRAPH + BM - 1) / BM);
        k_gemm<MODE_PLAIN, true><<<gd1, 256>>>(mu, dec_w1 + (size_t)i * D * DECH,
                                         dec_b1 + (size_t)i * DECH,
                                         zdec, nullptr, nullptr,
                                         NGRAPH, DECH, D, DECH, DECH, DECH,
                                         nullptr, nullptr);
        k_zero<<<(2432 + TB - 1) / TB, TB>>>(stats, 2432);
        dim3 grd((DECH + TB - 1) / TB, (NGRAPH + RED_ROWS - 1) / RED_ROWS);
        k_colreduce<<<grd, TB>>>(zdec, NGRAPH, DECH, stats);
        k_bnparam<<<(DECH + TB - 1) / TB, TB>>>(stats, dec_bng + (size_t)i * DECH,
                                                dec_bnb + (size_t)i * DECH,
                                                DECH, 1.0f / NGRAPH, bnA, bnB);
        dim3 gd2((ddims[i] + BN - 1) / BN, (NGRAPH + BM - 1) / BM);
        k_gemm<MODE_DEC, false><<<gd2, 256>>>(zdec, dec_w2 + (size_t)i * DECH * MAXO,
                                       dec_b2 + (size_t)i * MAXO,
                                       out + dbase[i], nullptr, nullptr,
                                       NGRAPH, ddims[i], DECH, MAXO, MAXO, dldc[i],
                                       bnA, bnB);
    }
}

// round 8
// speedup vs baseline: 1.9681x; 1.9681x over previous
#include <cuda_runtime.h>
#include <cuda_bf16.h>
#include <math.h>
#include <stdint.h>

#define NNODE 100000
#define NEDGE 200000
#define NGRAPH 4096
#define D 300
#define NLAYER 5
#define HDIM 600
#define DECH 1200
#define MAXO 1783
#define D4 (D/4)

// ---------------- scratch arenas (no cudaMalloc allowed) ----------------
#define OFF_H     0ull
#define OFF_Z     30000000ull
#define OFF_Z1    60000000ull
#define OFF_Z2    120000000ull
#define OFF_HG    150000000ull
#define OFF_MU    151228800ull
#define OFF_ZDEC  152457600ull
#define OFF_STATS 157372800ull
#define OFF_BNA   157375232ull
#define OFF_BNB   157376448ull
#define SCRATCH_FLOATS 157377664ull

__device__ float g_scratch[SCRATCH_FLOATS];

// A' split-bf16: encoder gemm2 needs 100000 x 1824 u16
__device__ __align__(16) unsigned short g_abf[182400000];

// W' split-bf16 weights, offsets in u16:
// w1: 5 x 640x960      = 5 x   614400
// w2: 5 x 384x1824     = 5 x   700416
// dist:    640x960     =       614400
// dec1: 6 x 1280x960   = 6 x  1228800
// dec2: 6 x 1792x3648  = 6 x  6537216
#define WO_W1(l)  ((size_t)(l) * 614400)
#define WO_W2(l)  (3072000ull + (size_t)(l) * 700416)
#define WO_DIST   6574080ull
#define WO_D1(i)  (7188480ull + (size_t)(i) * 1228800)
#define WO_D2(i)  (14561280ull + (size_t)(i) * 6537216)
__device__ __align__(16) unsigned short g_wbf[53784576];

__device__ __forceinline__ uint32_t smem_u32(const void* p) {
    uint32_t a;
    asm("{ .reg .u64 t; cvta.to.shared.u64 t, %1; cvt.u32.u64 %0, t; }" : "=r"(a) : "l"(p));
    return a;
}

#define LDSM4(r, addr) \
    asm volatile("ldmatrix.sync.aligned.m8n8.x4.shared.b16 {%0,%1,%2,%3}, [%4];" \
        : "=r"((r)[0]), "=r"((r)[1]), "=r"((r)[2]), "=r"((r)[3]) : "r"(addr))

#define MMA_BF16(d, a, b0, b1) \
    asm volatile("mma.sync.aligned.m16n8k16.row.col.f32.bf16.bf16.f32 " \
        "{%0,%1,%2,%3}, {%4,%5,%6,%7}, {%8,%9}, {%0,%1,%2,%3};" \
        : "+f"((d)[0]), "+f"((d)[1]), "+f"((d)[2]), "+f"((d)[3]) \
        : "r"((a)[0]), "r"((a)[1]), "r"((a)[2]), "r"((a)[3]), "r"(b0), "r"(b1))

#define CPASYNC16(dst, src, sz) \
    asm volatile("cp.async.cg.shared.global [%0], [%1], 16, %2;" \
        :: "r"(dst), "l"(src), "r"(sz))
#define CPCOMMIT() asm volatile("cp.async.commit_group;")
#define CPWAIT1()  asm volatile("cp.async.wait_group 1;")

// ---------------- small elementwise kernels ----------------

__global__ void k_gather(const float* __restrict__ atom_emb,
                         const int* __restrict__ x_idx,
                         float* __restrict__ h) {
    int t = blockIdx.x * blockDim.x + threadIdx.x;
    if (t >= NNODE * D4) return;
    int i = t / D4;
    int c = (t - i * D4) * 4;
    int a = x_idx[i];
    float4 v = *reinterpret_cast<const float4*>(atom_emb + (size_t)a * D + c);
    *reinterpret_cast<float4*>(h + (size_t)i * D + c) = v;
}

__global__ void k_scale(const float* __restrict__ h,
                        const float* __restrict__ eps, int l,
                        float* __restrict__ z) {
    int t = blockIdx.x * blockDim.x + threadIdx.x;
    if (t >= NNODE * D4) return;
    float s = 1.0f + eps[l];
    float4 v = *reinterpret_cast<const float4*>(h + (size_t)t * 4);
    v.x *= s; v.y *= s; v.z *= s; v.w *= s;
    *reinterpret_cast<float4*>(z + (size_t)t * 4) = v;
}

__global__ void k_edge(const float* __restrict__ h,
                       const float* __restrict__ emb,
                       const int* __restrict__ attr,
                       const int* __restrict__ eidx,
                       float* __restrict__ z) {
    int t = blockIdx.x * blockDim.x + threadIdx.x;
    if (t >= NEDGE * D4) return;
    int e = t / D4;
    int c = (t - e * D4) * 4;
    int src = eidx[e];
    int dst = eidx[NEDGE + e];
    int a = attr[e];
    float4 hv = *reinterpret_cast<const float4*>(h + (size_t)src * D + c);
    float4 ev = *reinterpret_cast<const float4*>(emb + (size_t)a * D + c);
    float m0 = fmaxf(hv.x + ev.x, 0.0f);
    float m1 = fmaxf(hv.y + ev.y, 0.0f);
    float m2 = fmaxf(hv.z + ev.z, 0.0f);
    float m3 = fmaxf(hv.w + ev.w, 0.0f);
    float* zp = z + (size_t)dst * D + c;
    atomicAdd(zp + 0, m0);
    atomicAdd(zp + 1, m1);
    atomicAdd(zp + 2, m2);
    atomicAdd(zp + 3, m3);
}

__global__ void k_zero(float* __restrict__ p, int n) {
    int t = blockIdx.x * blockDim.x + threadIdx.x;
    if (t < n) p[t] = 0.0f;
}

#define RED_ROWS 512
__global__ void k_colreduce(const float* __restrict__ X, int M, int Nc,
                            float* __restrict__ stats) {
    int c = blockIdx.x * blockDim.x + threadIdx.x;
    if (c >= Nc) return;
    int r0 = blockIdx.y * RED_ROWS;
    int r1 = r0 + RED_ROWS; if (r1 > M) r1 = M;
    float s = 0.0f, s2 = 0.0f;
    for (int r = r0; r < r1; r++) {
        float v = X[(size_t)r * Nc + c];
        s += v;
        s2 += v * v;
    }
    atomicAdd(&stats[c], s);
    atomicAdd(&stats[Nc + c], s2);
}

__global__ void k_bnparam(const float* __restrict__ stats,
                          const float* __restrict__ g,
                          const float* __restrict__ b,
                          int Nc, float invM,
                          float* __restrict__ bnA, float* __restrict__ bnB) {
    int c = blockIdx.x * blockDim.x + threadIdx.x;
    if (c >= Nc) return;
    float mean = stats[c] * invM;
    float var = stats[Nc + c] * invM - mean * mean;
    float a = g[c] * rsqrtf(var + 1e-5f);
    bnA[c] = a;
    bnB[c] = b[c] - mean * a;
}

__global__ void k_finalize(const float* __restrict__ z2,
                           const float* __restrict__ bnA,
                           const float* __restrict__ bnB,
                           int dorelu, float* __restrict__ h) {
    int t = blockIdx.x * blockDim.x + threadIdx.x;
    if (t >= NNODE * D4) return;
    size_t base = (size_t)t * 4;
    int c = (int)(base % D);
    float4 zv = *reinterpret_cast<const float4*>(z2 + base);
    float4 hv = *reinterpret_cast<const float4*>(h + base);
    float v0 = bnA[c + 0] * zv.x + bnB[c + 0];
    float v1 = bnA[c + 1] * zv.y + bnB[c + 1];
    float v2 = bnA[c + 2] * zv.z + bnB[c + 2];
    float v3 = bnA[c + 3] * zv.w + bnB[c + 3];
    if (dorelu) {
        v0 = fmaxf(v0, 0.0f); v1 = fmaxf(v1, 0.0f);
        v2 = fmaxf(v2, 0.0f); v3 = fmaxf(v3, 0.0f);
    }
    hv.x += v0; hv.y += v1; hv.z += v2; hv.w += v3;
    *reinterpret_cast<float4*>(h + base) = hv;
}

__global__ void k_hginit(float* __restrict__ hg) {
    int t = blockIdx.x * blockDim.x + threadIdx.x;
    if (t < NGRAPH * D) hg[t] = -INFINITY;
}

__device__ __forceinline__ void atomicMaxF(float* addr, float v) {
    if (v >= 0.0f) atomicMax((int*)addr, __float_as_int(v));
    else atomicMin((unsigned int*)addr, __float_as_uint(v));
}

__global__ void k_segmax(const float* __restrict__ h,
                         const int* __restrict__ batch,
                         float* __restrict__ hg) {
    int t = blockIdx.x * blockDim.x + threadIdx.x;
    if (t >= NNODE * D4) return;
    int i = t / D4;
    int c = (t - i * D4) * 4;
    int g = batch[i];
    float4 v = *reinterpret_cast<const float4*>(h + (size_t)i * D + c);
    float* p = hg + (size_t)g * D + c;
    atomicMaxF(p + 0, v.x);
    atomicMaxF(p + 1, v.y);
    atomicMaxF(p + 2, v.z);
    atomicMaxF(p + 3, v.w);
}

// ---------------- bf16 split conversion ----------------

__device__ __forceinline__ unsigned pk2bf(float a, float b) {
    unsigned short ua = __bfloat16_as_ushort(__float2bfloat16(a));
    unsigned short ub = __bfloat16_as_ushort(__float2bfloat16(b));
    return (unsigned)ua | ((unsigned)ub << 16);
}

// A': sections [Ah | Al | Ah]. PRE: 0 none, 1 bn+relu, 2 silu, 3 bn+gelu
template <int PRE>
__global__ void k_convA_bf(const float* __restrict__ X, int ldx, int Kin, int Kpad,
                           int Mrows,
                           const float* __restrict__ bnA, const float* __restrict__ bnB,
                           unsigned short* __restrict__ out, int kpitch) {
    int groups = Kpad >> 3;
    int t = blockIdx.x * blockDim.x + threadIdx.x;
    if (t >= Mrows * groups) return;
    int m = t / groups;
    int ko = (t - m * groups) << 3;
    const float* xr = X + (size_t)m * ldx;
    float hi[8], lo[8];
#pragma unroll
    for (int j = 0; j < 8; j++) {
        int k = ko + j;
        float x = 0.0f;
        if (k < Kin) {
            x = xr[k];
            if (PRE == 1) x = fmaxf(fmaf(bnA[k], x, bnB[k]), 0.0f);
            else if (PRE == 2) x = x / (1.0f + expf(-x));
            else if (PRE == 3) {
                float u = fmaf(bnA[k], x, bnB[k]);
                x = 0.5f * u * (1.0f + erff(u * 0.70710678118654752f));
            }
        }
        __nv_bfloat16 h = __float2bfloat16(x);
        float hf = __bfloat162float(h);
        hi[j] = hf;
        lo[j] = x - hf;
    }
    uint4 H, L;
    H.x = pk2bf(hi[0], hi[1]); H.y = pk2bf(hi[2], hi[3]);
    H.z = pk2bf(hi[4], hi[5]); H.w = pk2bf(hi[6], hi[7]);
    L.x = pk2bf(lo[0], lo[1]); L.y = pk2bf(lo[2], lo[3]);
    L.z = pk2bf(lo[4], lo[5]); L.w = pk2bf(lo[6], lo[7]);
    unsigned short* row = out + (size_t)m * kpitch + ko;
    *reinterpret_cast<uint4*>(row) = H;
    *reinterpret_cast<uint4*>(row + Kpad) = L;
    *reinterpret_cast<uint4*>(row + 2 * Kpad) = H;
}

// W': [Npad][3*Kpad] n-major, sections [Bh | Bh | Bl]
__global__ void k_convW_bf(const float* __restrict__ W, int ldw, int Kin, int Kpad,
                           int Nout, int Npad, unsigned short* __restrict__ out) {
    int groups = Kpad >> 3;
    int t = blockIdx.x * blockDim.x + threadIdx.x;
    if (t >= Npad * groups) return;
    int n = t / groups;
    int ko = (t - n * groups) << 3;
    float hi[8], lo[8];
#pragma unroll
    for (int j = 0; j < 8; j++) {
        int k = ko + j;
        float x = (n < Nout && k < Kin) ? W[(size_t)k * ldw + n] : 0.0f;
        __nv_bfloat16 h = __float2bfloat16(x);
        float hf = __bfloat162float(h);
        hi[j] = hf;
        lo[j] = x - hf;
    }
    uint4 H, L;
    H.x = pk2bf(hi[0], hi[1]); H.y = pk2bf(hi[2], hi[3]);
    H.z = pk2bf(hi[4], hi[5]); H.w = pk2bf(hi[6], hi[7]);
    L.x = pk2bf(lo[0], lo[1]); L.y = pk2bf(lo[2], lo[3]);
    L.z = pk2bf(lo[4], lo[5]); L.w = pk2bf(lo[6], lo[7]);
    int kpitch = 3 * Kpad;
    unsigned short* row = out + (size_t)n * kpitch + ko;
    *reinterpret_cast<uint4*>(row) = H;
    *reinterpret_cast<uint4*>(row + Kpad) = H;
    *reinterpret_cast<uint4*>(row + 2 * Kpad) = L;
}

// ---------------- HMMA GEMM: 128x128 CTA tile, k32 slabs, 3-stage cp.async ----
// MODE 0: C[r*ldc+c] = acc + bias[c]   (float2; Nreal,ldc even)
// MODE 2: dist: c<300 -> C & C3; 300<=c<600 -> softplus -> C2  (scalar)
// MODE 3: dec2: scalar bounded stores, odd ldc/Nreal ok
// smem per stage: A 128x80B (64B data + 16B pad) + B same = 20480B; 3 stages.

#define HSTAGE 20480
#define HSMEM  61440

template <int MODE>
__global__ void __launch_bounds__(256, 2)
k_hmma(const unsigned short* __restrict__ Ab, const unsigned short* __restrict__ Bb,
       const float* __restrict__ bias, float* __restrict__ C,
       float* __restrict__ C2, float* __restrict__ C3,
       int M, int Nreal, int ldc, int kpitch, int nk) {
    extern __shared__ __align__(16) char smem[];
    uint32_t sb = smem_u32(smem);
    int tid = threadIdx.x;
    int lane = tid & 31;
    int warp = tid >> 5;
    int wm = warp & 1;
    int wn = warp >> 1;
    int mtile = blockIdx.y;
    int ntile = blockIdx.x;

    // loader map: 512 chunks (16B) per operand per slab; thread -> chunks tid, tid+256
    int r0 = tid >> 2, q0 = tid & 3;
    int r1 = (tid + 256) >> 2, q1 = q0;      // (tid+256)&3 == tid&3
    const char* Ag0 = (const char*)(Ab + (size_t)(mtile * 128 + r0) * kpitch) + q0 * 16;
    const char* Ag1 = (const char*)(Ab + (size_t)(mtile * 128 + r1) * kpitch) + q1 * 16;
    const char* Bg0 = (const char*)(Bb + (size_t)(ntile * 128 + r0) * kpitch) + q0 * 16;
    const char* Bg1 = (const char*)(Bb + (size_t)(ntile * 128 + r1) * kpitch) + q1 * 16;
    unsigned a0sz = ((mtile * 128 + r0) < M) ? 16u : 0u;
    unsigned a1sz = ((mtile * 128 + r1) < M) ? 16u : 0u;
    uint32_t dA0 = r0 * 80 + q0 * 16;
    uint32_t dA1 = r1 * 80 + q1 * 16;

    float acc[4][4][4];
#pragma unroll
    for (int i = 0; i < 4; i++)
#pragma unroll
        for (int j = 0; j < 4; j++)
#pragma unroll
            for (int q = 0; q < 4; q++) acc[i][j][q] = 0.0f;

#define H_ISSUE(slab, buf) do { \
    uint32_t _b = sb + (buf) * HSTAGE; \
    size_t _o = (size_t)(slab) * 64; \
    CPASYNC16(_b + dA0, Ag0 + _o, a0sz); \
    CPASYNC16(_b + dA1, Ag1 + _o, a1sz); \
    CPASYNC16(_b + 10240 + dA0, Bg0 + _o, 16u); \
    CPASYNC16(_b + 10240 + dA1, Bg1 + _o, 16u); \
} while (0)

    // prologue: slabs 0,1
    H_ISSUE(0, 0); CPCOMMIT();
    H_ISSUE(1, 1); CPCOMMIT();

    uint32_t arow = (wm * 64 + (lane & 15)) * 80;
    uint32_t brow = (wn * 32 + (lane & 15)) * 80;
    uint32_t kcol = (lane >> 4) * 16;

    int buf = 0;
    for (int kt = 0; kt < nk; kt++) {
        CPWAIT1();
        __syncthreads();
        int ns = kt + 2;
        int nbuf = buf + 2; if (nbuf >= 3) nbuf -= 3;
        if (ns < nk) H_ISSUE(ns, nbuf);
        CPCOMMIT();

        uint32_t abase = sb + buf * HSTAGE;
        uint32_t bbase = abase + 10240;
#pragma unroll
        for (int ksub = 0; ksub < 2; ksub++) {
            uint32_t ko = kcol + ksub * 32;
            uint32_t b[2][4];
            LDSM4(b[0], bbase + brow + ko);
            LDSM4(b[1], bbase + brow + 1280 + ko);
#pragma unroll
            for (int mi = 0; mi < 4; mi++) {
                uint32_t a[4];
                LDSM4(a, abase + arow + mi * 1280 + ko);
#pragma unroll
                for (int nj = 0; nj < 4; nj++) {
                    uint32_t b0 = (nj & 1) ? b[nj >> 1][1] : b[nj >> 1][0];
                    uint32_t b1 = (nj & 1) ? b[nj >> 1][3] : b[nj >> 1][2];
                    MMA_BF16(acc[mi][nj], a, b0, b1);
                }
            }
        }
        buf++; if (buf == 3) buf = 0;
    }
#undef H_ISSUE

    // epilogue
    int g = lane >> 2, tig = lane & 3;
#pragma unroll
    for (int nj = 0; nj < 4; nj++) {
        int c = ntile * 128 + wn * 32 + nj * 8 + tig * 2;
#pragma unroll
        for (int mi = 0; mi < 4; mi++) {
            int rr0 = mtile * 128 + wm * 64 + mi * 16 + g;
            int rr1 = rr0 + 8;
            if (MODE == 0) {
                if (c < Nreal) {
                    float bc0 = bias[c], bc1 = bias[c + 1];
                    if (rr0 < M) {
                        float2 v; v.x = acc[mi][nj][0] + bc0; v.y = acc[mi][nj][1] + bc1;
                        *reinterpret_cast<float2*>(C + (size_t)rr0 * ldc + c) = v;
                    }
                    if (rr1 < M) {
                        float2 v; v.x = acc[mi][nj][2] + bc0; v.y = acc[mi][nj][3] + bc1;
                        *reinterpret_cast<float2*>(C + (size_t)rr1 * ldc + c) = v;
                    }
                }
            } else {
#pragma unroll
                for (int e = 0; e < 2; e++) {
                    int cc = c + e;
                    if (cc >= Nreal) continue;
                    float bv = bias[cc];
#pragma unroll
                    for (int half = 0; half < 2; half++) {
                        int r = half ? rr1 : rr0;
                        if (r >= M) continue;
                        float v = acc[mi][nj][half * 2 + e] + bv;
                        if (MODE == 2) {
                            if (cc < D) {
                                C[(size_t)r * ldc + cc] = v;
                                C3[(size_t)r * D + cc] = v;
                            } else {
                                float sp = fmaxf(v, 0.0f) + log1pf(expf(-fabsf(v))) + 1e-7f;
                                C2[(size_t)r * ldc + (cc - D)] = sp;
                            }
                        } else {
                            C[(size_t)r * ldc + cc] = v;
                        }
                    }
                }
            }
        }
    }
}

// ---------------- host side ----------------

extern "C" void kernel_launch(void* const* d_in, const int* in_sizes, int n_in,
                              void* d_out, int out_size) {
    const float* atom_emb = (const float*)d_in[0];
    const float* edge_emb = (const float*)d_in[1];
    const float* eps      = (const float*)d_in[2];
    const float* conv_w1  = (const float*)d_in[3];
    const float* conv_b1  = (const float*)d_in[4];
    const float* bn1g     = (const float*)d_in[5];
    const float* bn1b     = (const float*)d_in[6];
    const float* conv_w2  = (const float*)d_in[7];
    const float* conv_b2  = (const float*)d_in[8];
    const float* bn_g     = (const float*)d_in[9];
    const float* bn_b     = (const float*)d_in[10];
    const float* dist_w   = (const float*)d_in[11];
    const float* dist_b   = (const float*)d_in[12];
    const float* dec_w1   = (const float*)d_in[13];
    const float* dec_b1   = (const float*)d_in[14];
    const float* dec_bng  = (const float*)d_in[15];
    const float* dec_bnb  = (const float*)d_in[16];
    const float* dec_w2   = (const float*)d_in[17];
    const float* dec_b2   = (const float*)d_in[18];
    const int* x_idx      = (const int*)d_in[19];
    const int* edge_attr  = (const int*)d_in[20];
    const int* edge_index = (const int*)d_in[21];
    const int* batch      = (const int*)d_in[22];
    float* out = (float*)d_out;

    void* sp = nullptr;
    cudaGetSymbolAddress(&sp, g_scratch);
    float* S = (float*)sp;
    float* h     = S + OFF_H;
    float* z     = S + OFF_Z;
    float* z1    = S + OFF_Z1;
    float* z2    = S + OFF_Z2;
    float* hg    = S + OFF_HG;
    float* mu    = S + OFF_MU;
    float* zdec  = S + OFF_ZDEC;
    float* stats = S + OFF_STATS;
    float* bnA   = S + OFF_BNA;
    float* bnB   = S + OFF_BNB;

    void* abp = nullptr; cudaGetSymbolAddress(&abp, g_abf);
    unsigned short* abf = (unsigned short*)abp;
    void* wbp = nullptr; cudaGetSymbolAddress(&wbp, g_wbf);
    unsigned short* wbf = (unsigned short*)wbp;

    static int attr_done = 0;
    if (!attr_done) {
        cudaFuncSetAttribute(k_hmma<0>, cudaFuncAttributeMaxDynamicSharedMemorySize, HSMEM);
        cudaFuncSetAttribute(k_hmma<2>, cudaFuncAttributeMaxDynamicSharedMemorySize, HSMEM);
        cudaFuncSetAttribute(k_hmma<3>, cudaFuncAttributeMaxDynamicSharedMemorySize, HSMEM);
        attr_done = 1;
    }

    const int TB = 256;
    const int gNode = (NNODE * D4 + TB - 1) / TB;
    const int gEdge = (NEDGE * D4 + TB - 1) / TB;
    const int MT_N = (NNODE + 127) / 128;   // 782
    const int MT_G = NGRAPH / 128;          // 32

    // ---- convert all weights to split-bf16 (every call; deterministic) ----
    for (int l = 0; l < NLAYER; l++) {
        int n1 = 640 * (320 / 8);
        k_convW_bf<<<(n1 + TB - 1) / TB, TB>>>(conv_w1 + (size_t)l * D * HDIM, HDIM,
                                               300, 320, 600, 640, wbf + WO_W1(l));
        int n2 = 384 * (608 / 8);
        k_convW_bf<<<(n2 + TB - 1) / TB, TB>>>(conv_w2 + (size_t)l * HDIM * D, D,
                                               600, 608, 300, 384, wbf + WO_W2(l));
    }
    {
        int nd = 640 * (320 / 8);
        k_convW_bf<<<(nd + TB - 1) / TB, TB>>>(dist_w, 2 * D, 300, 320, 600, 640,
                                               wbf + WO_DIST);
    }
    const int ddims[6] = {1024, 1111, 862, 1783, 966, 978};
    for (int i = 0; i < 6; i++) {
        int na = 1280 * (320 / 8);
        k_convW_bf<<<(na + TB - 1) / TB, TB>>>(dec_w1 + (size_t)i * D * DECH, DECH,
                                               300, 320, 1200, 1280, wbf + WO_D1(i));
        int nb = 1792 * (1216 / 8);
        k_convW_bf<<<(nb + TB - 1) / TB, TB>>>(dec_w2 + (size_t)i * DECH * MAXO, MAXO,
                                               1200, 1216, ddims[i], 1792, wbf + WO_D2(i));
    }

    // ---- encoder ----
    k_gather<<<gNode, TB>>>(atom_emb, x_idx, h);

    for (int l = 0; l < NLAYER; l++) {
        k_scale<<<gNode, TB>>>(h, eps, l, z);
        k_edge<<<gEdge, TB>>>(h, edge_emb + (size_t)l * 5 * D, edge_attr, edge_index, z);

        // z1 = z @ w1 + b1
        {
            int nt = NNODE * (320 / 8);
            k_convA_bf<0><<<(nt + TB - 1) / TB, TB>>>(z, D, 300, 320, NNODE,
                                                      nullptr, nullptr, abf, 960);
            k_hmma<0><<<dim3(5, MT_N), 256, HSMEM>>>(abf, wbf + WO_W1(l),
                conv_b1 + (size_t)l * HDIM, z1, nullptr, nullptr,
                NNODE, 600, 600, 960, 30);
        }
        k_zero<<<(2432 + TB - 1) / TB, TB>>>(stats, 2432);
        dim3 gr1((HDIM + TB - 1) / TB, (NNODE + RED_ROWS - 1) / RED_ROWS);
        k_colreduce<<<gr1, TB>>>(z1, NNODE, HDIM, stats);
        k_bnparam<<<(HDIM + TB - 1) / TB, TB>>>(stats, bn1g + (size_t)l * HDIM,
                                                bn1b + (size_t)l * HDIM,
                                                HDIM, 1.0f / NNODE, bnA, bnB);
        // z2 = relu(bn(z1)) @ w2 + b2
        {
            int nt = NNODE * (608 / 8);
            k_convA_bf<1><<<(nt + TB - 1) / TB, TB>>>(z1, HDIM, 600, 608, NNODE,
                                                      bnA, bnB, abf, 1824);
            k_hmma<0><<<dim3(3, MT_N), 256, HSMEM>>>(abf, wbf + WO_W2(l),
                conv_b2 + (size_t)l * D, z2, nullptr, nullptr,
                NNODE, 300, 300, 1824, 57);
        }
        k_zero<<<(2432 + TB - 1) / TB, TB>>>(stats, 2432);
        dim3 gr2((D + TB - 1) / TB, (NNODE + RED_ROWS - 1) / RED_ROWS);
        k_colreduce<<<gr2, TB>>>(z2, NNODE, D, stats);
        k_bnparam<<<(D + TB - 1) / TB, TB>>>(stats, bn_g + (size_t)l * D,
                                             bn_b + (size_t)l * D,
                                             D, 1.0f / NNODE, bnA, bnB);
        k_finalize<<<gNode, TB>>>(z2, bnA, bnB, (l < NLAYER - 1) ? 1 : 0, h);
    }

    // ---- pooling + dist head ----
    k_hginit<<<(NGRAPH * D + TB - 1) / TB, TB>>>(hg);
    k_segmax<<<gNode, TB>>>(h, batch, hg);

    {
        int nt = NGRAPH * (320 / 8);
        k_convA_bf<2><<<(nt + TB - 1) / TB, TB>>>(hg, D, 300, 320, NGRAPH,
                                                  nullptr, nullptr, abf, 960);
        k_hmma<2><<<dim3(5, MT_G), 256, HSMEM>>>(abf, wbf + WO_DIST,
            dist_b, out, out + (size_t)NGRAPH * D, mu,
            NGRAPH, 600, 300, 960, 30);
    }

    // ---- decoders ----
    const size_t dbase[6] = {
        2457600ull,
        6651904ull,
        6651904ull + 1111ull,
        14733312ull,
        14733312ull + 1783ull,
        25993216ull
    };
    const int dldc[6] = {1024, 1973, 1973, 2749, 2749, 978};

    // mu conversion is decoder-invariant (kpitch 960); zdec uses a second region
    {
        int nt = NGRAPH * (320 / 8);
        k_convA_bf<0><<<(nt + TB - 1) / TB, TB>>>(mu, D, 300, 320, NGRAPH,
                                                  nullptr, nullptr, abf, 960);
    }
    unsigned short* abf2 = abf + (size_t)NGRAPH * 960;   // after mu tiles

    for (int i = 0; i < 6; i++) {
        k_hmma<0><<<dim3(10, MT_G), 256, HSMEM>>>(abf, wbf + WO_D1(i),
            dec_b1 + (size_t)i * DECH, zdec, nullptr, nullptr,
            NGRAPH, 1200, 1200, 960, 30);
        k_zero<<<(2432 + TB - 1) / TB, TB>>>(stats, 2432);
        dim3 grd((DECH + TB - 1) / TB, (NGRAPH + RED_ROWS - 1) / RED_ROWS);
        k_colreduce<<<grd, TB>>>(zdec, NGRAPH, DECH, stats);
        k_bnparam<<<(DECH + TB - 1) / TB, TB>>>(stats, dec_bng + (size_t)i * DECH,
                                                dec_bnb + (size_t)i * DECH,
                                                DECH, 1.0f / NGRAPH, bnA, bnB);
        {
            int nt = NGRAPH * (1216 / 8);
            k_convA_bf<3><<<(nt + TB - 1) / TB, TB>>>(zdec, DECH, 1200, 1216, NGRAPH,
                                                      bnA, bnB, abf2, 3648);
            k_hmma<3><<<dim3(14, MT_G), 256, HSMEM>>>(abf2, wbf + WO_D2(i),
                dec_b2 + (size_t)i * MAXO, out + dbase[i], nullptr, nullptr,
                NGRAPH, ddims[i], dldc[i], 3648, 114);
        }
    }
}

// round 9
// speedup vs baseline: 2.1561x; 1.0956x over previous
#include <cuda_runtime.h>
#include <cuda_bf16.h>
#include <math.h>
#include <stdint.h>

#define NNODE 100000
#define NEDGE 200000
#define NGRAPH 4096
#define D 300
#define NLAYER 5
#define HDIM 600
#define DECH 1200
#define MAXO 1783
#define D4 (D/4)

// ---------------- scratch arena (no cudaMalloc allowed) ----------------
#define OFF_H     0ull
#define OFF_Z     30000000ull
#define OFF_Z1    60000000ull
#define OFF_Z2    120000000ull
#define OFF_HG    150000000ull
#define OFF_MU    151228800ull
#define OFF_ZDEC  152457600ull
#define OFF_STATS 157372800ull
#define OFF_BNA   157375232ull
#define OFF_BNB   157376448ull
#define SCRATCH_FLOATS 157377664ull

__device__ float g_scratch[SCRATCH_FLOATS];

// W' split-bf16 weights, layout [Npad][2*Kpad] u16, row = [Bh | Bl]
// w1: 5 x 640*640   dist: 640*640   w2: 5 x 384*1216
// dec1: 6 x 1280*640   dec2: 6 x 1792*2432
#define WO_W1(l)  ((size_t)(l) * 409600)
#define WO_W2(l)  (2048000ull + (size_t)(l) * 466944)
#define WO_DIST   4382720ull
#define WO_D1(i)  (4792320ull + (size_t)(i) * 819200)
#define WO_D2(i)  (9707520ull + (size_t)(i) * 4358144)
__device__ __align__(16) unsigned short g_wbf[35856384];

__device__ __forceinline__ uint32_t smem_u32(const void* p) {
    uint32_t a;
    asm("{ .reg .u64 t; cvta.to.shared.u64 t, %1; cvt.u32.u64 %0, t; }" : "=r"(a) : "l"(p));
    return a;
}

#define LDSM4(r, addr) \
    asm volatile("ldmatrix.sync.aligned.m8n8.x4.shared.b16 {%0,%1,%2,%3}, [%4];" \
        : "=r"((r)[0]), "=r"((r)[1]), "=r"((r)[2]), "=r"((r)[3]) : "r"(addr))

#define MMA_BF16(d, a, b0, b1) \
    asm volatile("mma.sync.aligned.m16n8k16.row.col.f32.bf16.bf16.f32 " \
        "{%0,%1,%2,%3}, {%4,%5,%6,%7}, {%8,%9}, {%0,%1,%2,%3};" \
        : "+f"((d)[0]), "+f"((d)[1]), "+f"((d)[2]), "+f"((d)[3]) \
        : "r"((a)[0]), "r"((a)[1]), "r"((a)[2]), "r"((a)[3]), "r"(b0), "r"(b1))

#define CPASYNC16(dst, src, sz) \
    asm volatile("cp.async.cg.shared.global [%0], [%1], 16, %2;" \
        :: "r"(dst), "l"(src), "r"(sz))
#define CPCOMMIT() asm volatile("cp.async.commit_group;")
#define CPWAIT2()  asm volatile("cp.async.wait_group 2;")

// ---------------- small elementwise kernels ----------------

__global__ void k_gather(const float* __restrict__ atom_emb,
                         const int* __restrict__ x_idx,
                         float* __restrict__ h) {
    int t = blockIdx.x * blockDim.x + threadIdx.x;
    if (t >= NNODE * D4) return;
    int i = t / D4;
    int c = (t - i * D4) * 4;
    int a = x_idx[i];
    float4 v = *reinterpret_cast<const float4*>(atom_emb + (size_t)a * D + c);
    *reinterpret_cast<float4*>(h + (size_t)i * D + c) = v;
}

__global__ void k_scale(const float* __restrict__ h,
                        const float* __restrict__ eps, int l,
                        float* __restrict__ z) {
    int t = blockIdx.x * blockDim.x + threadIdx.x;
    if (t >= NNODE * D4) return;
    float s = 1.0f + eps[l];
    float4 v = *reinterpret_cast<const float4*>(h + (size_t)t * 4);
    v.x *= s; v.y *= s; v.z *= s; v.w *= s;
    *reinterpret_cast<float4*>(z + (size_t)t * 4) = v;
}

__global__ void k_edge(const float* __restrict__ h,
                       const float* __restrict__ emb,
                       const int* __restrict__ attr,
                       const int* __restrict__ eidx,
                       float* __restrict__ z) {
    int t = blockIdx.x * blockDim.x + threadIdx.x;
    if (t >= NEDGE * D4) return;
    int e = t / D4;
    int c = (t - e * D4) * 4;
    int src = eidx[e];
    int dst = eidx[NEDGE + e];
    int a = attr[e];
    float4 hv = *reinterpret_cast<const float4*>(h + (size_t)src * D + c);
    float4 ev = *reinterpret_cast<const float4*>(emb + (size_t)a * D + c);
    float m0 = fmaxf(hv.x + ev.x, 0.0f);
    float m1 = fmaxf(hv.y + ev.y, 0.0f);
    float m2 = fmaxf(hv.z + ev.z, 0.0f);
    float m3 = fmaxf(hv.w + ev.w, 0.0f);
    float* zp = z + (size_t)dst * D + c;
    atomicAdd(zp + 0, m0);
    atomicAdd(zp + 1, m1);
    atomicAdd(zp + 2, m2);
    atomicAdd(zp + 3, m3);
}

__global__ void k_zero(float* __restrict__ p, int n) {
    int t = blockIdx.x * blockDim.x + threadIdx.x;
    if (t < n) p[t] = 0.0f;
}

__global__ void k_bnparam(const float* __restrict__ stats,
                          const float* __restrict__ g,
                          const float* __restrict__ b,
                          int Nc, float invM,
                          float* __restrict__ bnA, float* __restrict__ bnB) {
    int c = blockIdx.x * blockDim.x + threadIdx.x;
    if (c >= Nc) return;
    float mean = stats[c] * invM;
    float var = stats[Nc + c] * invM - mean * mean;
    float a = g[c] * rsqrtf(var + 1e-5f);
    bnA[c] = a;
    bnB[c] = b[c] - mean * a;
}

__global__ void k_finalize(const float* __restrict__ z2,
                           const float* __restrict__ bnA,
                           const float* __restrict__ bnB,
                           int dorelu, float* __restrict__ h) {
    int t = blockIdx.x * blockDim.x + threadIdx.x;
    if (t >= NNODE * D4) return;
    size_t base = (size_t)t * 4;
    int c = (int)(base % D);
    float4 zv = *reinterpret_cast<const float4*>(z2 + base);
    float4 hv = *reinterpret_cast<const float4*>(h + base);
    float v0 = bnA[c + 0] * zv.x + bnB[c + 0];
    float v1 = bnA[c + 1] * zv.y + bnB[c + 1];
    float v2 = bnA[c + 2] * zv.z + bnB[c + 2];
    float v3 = bnA[c + 3] * zv.w + bnB[c + 3];
    if (dorelu) {
        v0 = fmaxf(v0, 0.0f); v1 = fmaxf(v1, 0.0f);
        v2 = fmaxf(v2, 0.0f); v3 = fmaxf(v3, 0.0f);
    }
    hv.x += v0; hv.y += v1; hv.z += v2; hv.w += v3;
    *reinterpret_cast<float4*>(h + base) = hv;
}

__global__ void k_hginit(float* __restrict__ hg) {
    int t = blockIdx.x * blockDim.x + threadIdx.x;
    if (t < NGRAPH * D) hg[t] = -INFINITY;
}

__device__ __forceinline__ void atomicMaxF(float* addr, float v) {
    if (v >= 0.0f) atomicMax((int*)addr, __float_as_int(v));
    else atomicMin((unsigned int*)addr, __float_as_uint(v));
}

__global__ void k_segmax(const float* __restrict__ h,
                         const int* __restrict__ batch,
                         float* __restrict__ hg) {
    int t = blockIdx.x * blockDim.x + threadIdx.x;
    if (t >= NNODE * D4) return;
    int i = t / D4;
    int c = (t - i * D4) * 4;
    int g = batch[i];
    float4 v = *reinterpret_cast<const float4*>(h + (size_t)i * D + c);
    float* p = hg + (size_t)g * D + c;
    atomicMaxF(p + 0, v.x);
    atomicMaxF(p + 1, v.y);
    atomicMaxF(p + 2, v.z);
    atomicMaxF(p + 3, v.w);
}

// ---------------- weight conversion: fp32 -> [Bh | Bl] n-major ----------------

__device__ __forceinline__ unsigned pk2bf(float a, float b) {
    unsigned short ua = __bfloat16_as_ushort(__float2bfloat16(a));
    unsigned short ub = __bfloat16_as_ushort(__float2bfloat16(b));
    return (unsigned)ua | ((unsigned)ub << 16);
}

__global__ void k_convW2(const float* __restrict__ W, int ldw, int Kin, int Kpad,
                         int Nout, int Npad, unsigned short* __restrict__ out) {
    int groups = Kpad >> 3;
    int t = blockIdx.x * blockDim.x + threadIdx.x;
    if (t >= Npad * groups) return;
    int n = t / groups;
    int ko = (t - n * groups) << 3;
    float hi[8], lo[8];
#pragma unroll
    for (int j = 0; j < 8; j++) {
        int k = ko + j;
        float x = (n < Nout && k < Kin) ? W[(size_t)k * ldw + n] : 0.0f;
        __nv_bfloat16 h = __float2bfloat16(x);
        float hf = __bfloat162float(h);
        hi[j] = hf;
        lo[j] = x - hf;
    }
    uint4 H, L;
    H.x = pk2bf(hi[0], hi[1]); H.y = pk2bf(hi[2], hi[3]);
    H.z = pk2bf(hi[4], hi[5]); H.w = pk2bf(hi[6], hi[7]);
    L.x = pk2bf(lo[0], lo[1]); L.y = pk2bf(lo[2], lo[3]);
    L.z = pk2bf(lo[4], lo[5]); L.w = pk2bf(lo[6], lo[7]);
    unsigned short* row = out + (size_t)n * 2 * Kpad + ko;
    *reinterpret_cast<uint4*>(row) = H;
    *reinterpret_cast<uint4*>(row + Kpad) = L;
}

// ---------------- fused-convert HMMA GEMM -------------------------------------
// A loaded as fp32 (register prefetch), PRE applied, split hi/lo into smem.
// Per k32 slab: AhBh + AlBh + AhBl MMA groups (full split-bf16 product).
// B = pre-converted [Bh|Bl] rows, 3-stage cp.async ring.
// MODE 0: C = acc + bias (float2 stores) ; optional fused column sum/sumsq -> stats
// MODE 2: dist head split (mu/softplus)   MODE 3: scalar bounded stores
// smem: A (Ah+Al) 20480 + B 3*20480 = 81920

#define FSMEM 81920

template <int MODE, int PRE>
__global__ void __launch_bounds__(256, 2)
k_hmma_f(const float* __restrict__ A, int lda, int Kin,
         const unsigned short* __restrict__ Bb, int Kpad,
         const float* __restrict__ bias,
         const float* __restrict__ bnA, const float* __restrict__ bnB,
         float* __restrict__ C, float* __restrict__ C2, float* __restrict__ C3,
         float* __restrict__ stats,
         int M, int Nreal, int ldc) {
    extern __shared__ __align__(16) char smem[];
    const int nk = Kpad >> 5;
    uint32_t sb = smem_u32(smem);       // Ah @0, Al @10240
    uint32_t sbB = sb + 20480;          // 3 stages: [Bh | Bl(+10240)]
    int tid = threadIdx.x;
    int lane = tid & 31;
    int warp = tid >> 5;
    int wm = warp & 1, wn = warp >> 1;
    int mtile = blockIdx.y, ntile = blockIdx.x;

    // A loader map: rows (tid>>3)+p*32, float4 col aq
    int arL = tid >> 3;
    int aq = tid & 7;
    const float* Abase = A + (size_t)(mtile * 128) * lda;
    float4 af[4];

    // B loader map
    int br = tid >> 2;
    int bq = tid & 3;
    size_t wpitch = (size_t)4 * Kpad;   // bytes per W' row
    const char* Bg0 = (const char*)Bb + (size_t)(ntile * 128 + br) * wpitch + bq * 16;
    const char* Bg1 = (const char*)Bb + (size_t)(ntile * 128 + br + 64) * wpitch + bq * 16;
    uint32_t dB0 = br * 80 + bq * 16;
    uint32_t dB1 = (br + 64) * 80 + bq * 16;
    uint32_t loff = (uint32_t)(2 * Kpad);   // Bl byte offset within row

#define B_ISSUE(slab, stg) do { \
    uint32_t _s = sbB + (stg) * 20480; \
    size_t _o = (size_t)(slab) * 64; \
    CPASYNC16(_s + dB0, Bg0 + _o, 16u); \
    CPASYNC16(_s + dB1, Bg1 + _o, 16u); \
    CPASYNC16(_s + 10240 + dB0, Bg0 + loff + _o, 16u); \
    CPASYNC16(_s + 10240 + dB1, Bg1 + loff + _o, 16u); \
} while (0)

    auto loadA = [&](int kt) {
        int k0 = kt * 32 + aq * 4;
        bool kok = (k0 < Kin);
#pragma unroll
        for (int p = 0; p < 4; p++) {
            int r = arL + p * 32;
            bool ok = kok && ((mtile * 128 + r) < M);
            af[p] = ok ? *reinterpret_cast<const float4*>(Abase + (size_t)r * lda + k0)
                       : make_float4(0.f, 0.f, 0.f, 0.f);
        }
    };
    auto storeA = [&](int kt) {
        int k0 = kt * 32 + aq * 4;
        bool kok = (k0 < Kin);
#pragma unroll
        for (int p = 0; p < 4; p++) {
            float x[4] = {af[p].x, af[p].y, af[p].z, af[p].w};
            if (kok) {
#pragma unroll
                for (int j = 0; j < 4; j++) {
                    if (PRE == 1) x[j] = fmaxf(fmaf(bnA[k0 + j], x[j], bnB[k0 + j]), 0.0f);
                    else if (PRE == 2) x[j] = x[j] / (1.0f + expf(-x[j]));
                    else if (PRE == 3) {
                        float u = fmaf(bnA[k0 + j], x[j], bnB[k0 + j]);
                        x[j] = 0.5f * u * (1.0f + erff(u * 0.70710678118654752f));
                    }
                }
            }
            float h[4], l[4];
#pragma unroll
            for (int j = 0; j < 4; j++) {
                __nv_bfloat16 hb = __float2bfloat16(x[j]);
                h[j] = __bfloat162float(hb);
                l[j] = x[j] - h[j];
            }
            unsigned H0 = pk2bf(h[0], h[1]), H1 = pk2bf(h[2], h[3]);
            unsigned L0 = pk2bf(l[0], l[1]), L1 = pk2bf(l[2], l[3]);
            int r = arL + p * 32;
            uint32_t ad = sb + r * 80 + aq * 8;
            asm volatile("st.shared.v2.b32 [%0], {%1,%2};" :: "r"(ad), "r"(H0), "r"(H1));
            asm volatile("st.shared.v2.b32 [%0], {%1,%2};" :: "r"(ad + 10240), "r"(L0), "r"(L1));
        }
    };

    float acc[4][4][4];
#pragma unroll
    for (int i = 0; i < 4; i++)
#pragma unroll
        for (int j = 0; j < 4; j++)
#pragma unroll
            for (int q = 0; q < 4; q++) acc[i][j][q] = 0.0f;

    // prologue
    loadA(0);
    B_ISSUE(0, 0); CPCOMMIT();
    B_ISSUE(1, 1); CPCOMMIT();

    uint32_t arow = (wm * 64 + (lane & 15)) * 80;
    uint32_t brow = (wn * 32 + (lane & 15)) * 80;
    uint32_t kcol = (lane >> 4) * 16;

    for (int kt = 0; kt < nk; kt++) {
        __syncthreads();                 // A smem free (prev MMA done)
        storeA(kt);
        if (kt + 1 < nk) loadA(kt + 1);
        {
            int ns = kt + 2;
            if (ns < nk) {
                int stg = ns - (ns / 3) * 3;
                B_ISSUE(ns, stg);
            }
            CPCOMMIT();
        }
        CPWAIT2();
        __syncthreads();                 // A stores + B(kt) visible

        uint32_t bstage = sbB + (kt - (kt / 3) * 3) * 20480;
#pragma unroll
        for (int ksub = 0; ksub < 2; ksub++) {
            uint32_t ko = kcol + ksub * 32;
            uint32_t bh[2][4], bl[2][4];
            LDSM4(bh[0], bstage + brow + ko);
            LDSM4(bh[1], bstage + brow + 1280 + ko);
            LDSM4(bl[0], bstage + 10240 + brow + ko);
            LDSM4(bl[1], bstage + 10240 + brow + 1280 + ko);
#pragma unroll
            for (int mi = 0; mi < 4; mi++) {
                uint32_t ah[4], al[4];
                LDSM4(ah, sb + arow + mi * 1280 + ko);
                LDSM4(al, sb + 10240 + arow + mi * 1280 + ko);
#pragma unroll
                for (int nj = 0; nj < 4; nj++) {
                    uint32_t b0 = (nj & 1) ? bh[nj >> 1][1] : bh[nj >> 1][0];
                    uint32_t b1 = (nj & 1) ? bh[nj >> 1][3] : bh[nj >> 1][2];
                    MMA_BF16(acc[mi][nj], ah, b0, b1);
                }
#pragma unroll
                for (int nj = 0; nj < 4; nj++) {
                    uint32_t b0 = (nj & 1) ? bh[nj >> 1][1] : bh[nj >> 1][0];
                    uint32_t b1 = (nj & 1) ? bh[nj >> 1][3] : bh[nj >> 1][2];
                    MMA_BF16(acc[mi][nj], al, b0, b1);
                }
#pragma unroll
                for (int nj = 0; nj < 4; nj++) {
                    uint32_t b0 = (nj & 1) ? bl[nj >> 1][1] : bl[nj >> 1][0];
                    uint32_t b1 = (nj & 1) ? bl[nj >> 1][3] : bl[nj >> 1][2];
                    MMA_BF16(acc[mi][nj], ah, b0, b1);
                }
            }
        }
    }
#undef B_ISSUE

    // epilogue
    int g = lane >> 2, tig = lane & 3;
#pragma unroll
    for (int nj = 0; nj < 4; nj++) {
        int c = ntile * 128 + wn * 32 + nj * 8 + tig * 2;
        if (MODE == 0) {
            bool cok = (c < Nreal);
            float bc0 = cok ? bias[c] : 0.0f;
            float bc1 = cok ? bias[c + 1] : 0.0f;
            float s0 = 0.f, q0 = 0.f, s1 = 0.f, q1 = 0.f;
#pragma unroll
            for (int mi = 0; mi < 4; mi++) {
                int rr0 = mtile * 128 + wm * 64 + mi * 16 + g;
                int rr1 = rr0 + 8;
                if (cok && rr0 < M) {
                    float v0 = acc[mi][nj][0] + bc0;
                    float v1 = acc[mi][nj][1] + bc1;
                    float2 t; t.x = v0; t.y = v1;
                    *reinterpret_cast<float2*>(C + (size_t)rr0 * ldc + c) = t;
                    s0 += v0; q0 += v0 * v0; s1 += v1; q1 += v1 * v1;
                }
                if (cok && rr1 < M) {
                    float v0 = acc[mi][nj][2] + bc0;
                    float v1 = acc[mi][nj][3] + bc1;
                    float2 t; t.x = v0; t.y = v1;
                    *reinterpret_cast<float2*>(C + (size_t)rr1 * ldc + c) = t;
                    s0 += v0; q0 += v0 * v0; s1 += v1; q1 += v1 * v1;
                }
            }
            if (stats) {
#pragma unroll
                for (int off = 16; off >= 4; off >>= 1) {
                    s0 += __shfl_down_sync(0xffffffffu, s0, off);
                    q0 += __shfl_down_sync(0xffffffffu, q0, off);
                    s1 += __shfl_down_sync(0xffffffffu, s1, off);
                    q1 += __shfl_down_sync(0xffffffffu, q1, off);
                }
                if (g == 0 && cok) {
                    atomicAdd(&stats[c], s0);
                    atomicAdd(&stats[Nreal + c], q0);
                    atomicAdd(&stats[c + 1], s1);
                    atomicAdd(&stats[Nreal + c + 1], q1);
                }
            }
        } else {
#pragma unroll
            for (int mi = 0; mi < 4; mi++) {
                int rr0 = mtile * 128 + wm * 64 + mi * 16 + g;
                int rr1 = rr0 + 8;
#pragma unroll
                for (int e = 0; e < 2; e++) {
                    int cc = c + e;
                    if (cc >= Nreal) continue;
                    float bv = bias[cc];
#pragma unroll
                    for (int half = 0; half < 2; half++) {
                        int r = half ? rr1 : rr0;
                        if (r >= M) continue;
                        float v = acc[mi][nj][half * 2 + e] + bv;
                        if (MODE == 2) {
                            if (cc < D) {
                                C[(size_t)r * ldc + cc] = v;
                                C3[(size_t)r * D + cc] = v;
                            } else {
                                float sp = fmaxf(v, 0.0f) + log1pf(expf(-fabsf(v))) + 1e-7f;
                                C2[(size_t)r * ldc + (cc - D)] = sp;
                            }
                        } else {
                            C[(size_t)r * ldc + cc] = v;
                        }
                    }
                }
            }
        }
    }
}

// ---------------- host side ----------------

extern "C" void kernel_launch(void* const* d_in, const int* in_sizes, int n_in,
                              void* d_out, int out_size) {
    const float* atom_emb = (const float*)d_in[0];
    const float* edge_emb = (const float*)d_in[1];
    const float* eps      = (const float*)d_in[2];
    const float* conv_w1  = (const float*)d_in[3];
    const float* conv_b1  = (const float*)d_in[4];
    const float* bn1g     = (const float*)d_in[5];
    const float* bn1b     = (const float*)d_in[6];
    const float* conv_w2  = (const float*)d_in[7];
    const float* conv_b2  = (const float*)d_in[8];
    const float* bn_g     = (const float*)d_in[9];
    const float* bn_b     = (const float*)d_in[10];
    const float* dist_w   = (const float*)d_in[11];
    const float* dist_b   = (const float*)d_in[12];
    const float* dec_w1   = (const float*)d_in[13];
    const float* dec_b1   = (const float*)d_in[14];
    const float* dec_bng  = (const float*)d_in[15];
    const float* dec_bnb  = (const float*)d_in[16];
    const float* dec_w2   = (const float*)d_in[17];
    const float* dec_b2   = (const float*)d_in[18];
    const int* x_idx      = (const int*)d_in[19];
    const int* edge_attr  = (const int*)d_in[20];
    const int* edge_index = (const int*)d_in[21];
    const int* batch      = (const int*)d_in[22];
    float* out = (float*)d_out;

    void* sp = nullptr;
    cudaGetSymbolAddress(&sp, g_scratch);
    float* S = (float*)sp;
    float* h     = S + OFF_H;
    float* z     = S + OFF_Z;
    float* z1    = S + OFF_Z1;
    float* z2    = S + OFF_Z2;
    float* hg    = S + OFF_HG;
    float* mu    = S + OFF_MU;
    float* zdec  = S + OFF_ZDEC;
    float* stats = S + OFF_STATS;
    float* bnA   = S + OFF_BNA;
    float* bnB   = S + OFF_BNB;

    void* wbp = nullptr; cudaGetSymbolAddress(&wbp, g_wbf);
    unsigned short* wbf = (unsigned short*)wbp;

    static int attr_done = 0;
    if (!attr_done) {
        cudaFuncSetAttribute(k_hmma_f<0, 0>, cudaFuncAttributeMaxDynamicSharedMemorySize, FSMEM);
        cudaFuncSetAttribute(k_hmma_f<0, 1>, cudaFuncAttributeMaxDynamicSharedMemorySize, FSMEM);
        cudaFuncSetAttribute(k_hmma_f<2, 2>, cudaFuncAttributeMaxDynamicSharedMemorySize, FSMEM);
        cudaFuncSetAttribute(k_hmma_f<3, 3>, cudaFuncAttributeMaxDynamicSharedMemorySize, FSMEM);
        attr_done = 1;
    }

    const int TB = 256;
    const int gNode = (NNODE * D4 + TB - 1) / TB;
    const int gEdge = (NEDGE * D4 + TB - 1) / TB;
    const int MT_N = (NNODE + 127) / 128;   // 782
    const int MT_G = NGRAPH / 128;          // 32

    // ---- convert all weights to [Bh|Bl] (every call; deterministic) ----
    for (int l = 0; l < NLAYER; l++) {
        int n1 = 640 * (320 / 8);
        k_convW2<<<(n1 + TB - 1) / TB, TB>>>(conv_w1 + (size_t)l * D * HDIM, HDIM,
                                             300, 320, 600, 640, wbf + WO_W1(l));
        int n2 = 384 * (608 / 8);
        k_convW2<<<(n2 + TB - 1) / TB, TB>>>(conv_w2 + (size_t)l * HDIM * D, D,
                                             600, 608, 300, 384, wbf + WO_W2(l));
    }
    {
        int nd = 640 * (320 / 8);
        k_convW2<<<(nd + TB - 1) / TB, TB>>>(dist_w, 2 * D, 300, 320, 600, 640,
                                             wbf + WO_DIST);
    }
    const int ddims[6] = {1024, 1111, 862, 1783, 966, 978};
    for (int i = 0; i < 6; i++) {
        int na = 1280 * (320 / 8);
        k_convW2<<<(na + TB - 1) / TB, TB>>>(dec_w1 + (size_t)i * D * DECH, DECH,
                                             300, 320, 1200, 1280, wbf + WO_D1(i));
        int nb = 1792 * (1216 / 8);
        k_convW2<<<(nb + TB - 1) / TB, TB>>>(dec_w2 + (size_t)i * DECH * MAXO, MAXO,
                                             1200, 1216, ddims[i], 1792, wbf + WO_D2(i));
    }

    // ---- encoder ----
    k_gather<<<gNode, TB>>>(atom_emb, x_idx, h);

    for (int l = 0; l < NLAYER; l++) {
        k_scale<<<gNode, TB>>>(h, eps, l, z);
        k_edge<<<gEdge, TB>>>(h, edge_emb + (size_t)l * 5 * D, edge_attr, edge_index, z);

        // z1 = z @ w1 + b1 (+ fused col stats)
        k_zero<<<(2432 + TB - 1) / TB, TB>>>(stats, 2432);
        k_hmma_f<0, 0><<<dim3(5, MT_N), 256, FSMEM>>>(
            z, D, 300, wbf + WO_W1(l), 320,
            conv_b1 + (size_t)l * HDIM, nullptr, nullptr,
            z1, nullptr, nullptr, stats, NNODE, 600, 600);
        k_bnparam<<<(HDIM + TB - 1) / TB, TB>>>(stats, bn1g + (size_t)l * HDIM,
                                                bn1b + (size_t)l * HDIM,
                                                HDIM, 1.0f / NNODE, bnA, bnB);
        // z2 = relu(bn(z1)) @ w2 + b2 (+ fused col stats)
        k_zero<<<(2432 + TB - 1) / TB, TB>>>(stats, 2432);
        k_hmma_f<0, 1><<<dim3(3, MT_N), 256, FSMEM>>>(
            z1, HDIM, 600, wbf + WO_W2(l), 608,
            conv_b2 + (size_t)l * D, bnA, bnB,
            z2, nullptr, nullptr, stats, NNODE, 300, 300);
        k_bnparam<<<(D + TB - 1) / TB, TB>>>(stats, bn_g + (size_t)l * D,
                                             bn_b + (size_t)l * D,
                                             D, 1.0f / NNODE, bnA, bnB);
        k_finalize<<<gNode, TB>>>(z2, bnA, bnB, (l < NLAYER - 1) ? 1 : 0, h);
    }

    // ---- pooling + dist head ----
    k_hginit<<<(NGRAPH * D + TB - 1) / TB, TB>>>(hg);
    k_segmax<<<gNode, TB>>>(h, batch, hg);

    k_hmma_f<2, 2><<<dim3(5, MT_G), 256, FSMEM>>>(
        hg, D, 300, wbf + WO_DIST, 320,
        dist_b, nullptr, nullptr,
        out, out + (size_t)NGRAPH * D, mu, nullptr, NGRAPH, 600, 300);

    // ---- decoders ----
    const size_t dbase[6] = {
        2457600ull,
        6651904ull,
        6651904ull + 1111ull,
        14733312ull,
        14733312ull + 1783ull,
        25993216ull
    };
    const int dldc[6] = {1024, 1973, 1973, 2749, 2749, 978};

    for (int i = 0; i < 6; i++) {
        k_zero<<<(2432 + TB - 1) / TB, TB>>>(stats, 2432);
        k_hmma_f<0, 0><<<dim3(10, MT_G), 256, FSMEM>>>(
            mu, D, 300, wbf + WO_D1(i), 320,
            dec_b1 + (size_t)i * DECH, nullptr, nullptr,
            zdec, nullptr, nullptr, stats, NGRAPH, 1200, 1200);
        k_bnparam<<<(DECH + TB - 1) / TB, TB>>>(stats, dec_bng + (size_t)i * DECH,
                                                dec_bnb + (size_t)i * DECH,
                                                DECH, 1.0f / NGRAPH, bnA, bnB);
        k_hmma_f<3, 3><<<dim3(14, MT_G), 256, FSMEM>>>(
            zdec, DECH, 1200, wbf + WO_D2(i), 1216,
            dec_b2 + (size_t)i * MAXO, bnA, bnB,
            out + dbase[i], nullptr, nullptr, nullptr, NGRAPH, ddims[i], dldc[i]);
    }
}